// round 13
// baseline (speedup 1.0000x reference)
#include <cuda_runtime.h>

#define KN 40
#define FN 32
#define VPW 8                 // vertices per warp (4 lanes per vertex)
#define WPB 4                 // warps per block
#define ASTR 41               // float4 stride per vertex in record array (stagger)
#define AN (VPW*ASTR)         // 328 record slots per warp
#define FBOFF (AN*4)          // float offset of fb array within warp smem = 1312
#define WSH (AN*4 + AN)       // floats per warp = 1640 (6.56 KB)
#define SSTR 404              // staging stride floats (101 float4: 5a+2s distinct mod 8)

__device__ float4 g_coords4[131072];   // padded coords scratch (V <= 131072)

__device__ __forceinline__ unsigned long long pack2(float lo, float hi) {
    unsigned long long r;
    asm("mov.b64 %0, {%1,%2};" : "=l"(r) : "f"(lo), "f"(hi));
    return r;
}
__device__ __forceinline__ void unpack2(unsigned long long v, float& lo, float& hi) {
    asm("mov.b64 {%0,%1}, %2;" : "=f"(lo), "=f"(hi) : "l"(v));
}
__device__ __forceinline__ unsigned long long ffma2(unsigned long long a,
                                                    unsigned long long b,
                                                    unsigned long long c) {
    unsigned long long d;
    asm("fma.rn.f32x2 %0, %1, %2, %3;" : "=l"(d) : "l"(a), "l"(b), "l"(c));
    return d;
}

__global__ void pad_coords_kernel(const float* __restrict__ c, int V) {
    int i = blockIdx.x * blockDim.x + threadIdx.x;
    if (i < V) {
        g_coords4[i] = make_float4(c[3*i], c[3*i+1], c[3*i+2], 0.f);
    }
}

__global__ __launch_bounds__(WPB * 32, 4)   // allow up to 128 regs, 4 blocks/SM
void nbcov_kernel(const float* __restrict__ distsq,
                  const float* __restrict__ feats,
                  const int* __restrict__ nidx,
                  float* __restrict__ out, int V)
{
    __shared__ float smem[WPB * WSH];
    const int warp = threadIdx.x >> 5;
    const int lane = threadIdx.x & 31;
    const int vbase = (blockIdx.x * WPB + warp) * VPW;
    float* ws = smem + warp * WSH;

    float4* A4  = (float4*)ws;               // [vloc*41+k]: (x, y, z, w)
    int*    fbA = (int*)(ws + FBOFF);        // [vloc*41+k]: ia*FN

    // ---------- prep: 320 (vertex,k) tasks per warp ----------
    #pragma unroll
    for (int t = 0; t < 10; ++t) {
        const int id = t * 32 + lane;          // 0..319, lexicographic (vloc,k)
        const int vloc = id / KN;
        const int k = id - vloc * KN;
        const int v = vbase + vloc;
        float w = 0.f;
        int ia = 0;
        float4 c4 = make_float4(0.f, 0.f, 0.f, 0.f);
        if (v < V) {
            const int ko = vbase * KN + id;    // contiguous, coalesced
            int t_ia = nidx[ko];
            float d = distsq[ko];
            if (t_ia >= 0) { w = __expf(-10.0f * d); ia = t_ia; }
            c4 = g_coords4[ia];                // single LDG.128 gather (irreducible)
        }
        const int ridx = vloc * ASTR + k;
        A4[ridx]  = make_float4(c4.x, c4.y, c4.z, w);
        fbA[ridx] = ia * FN;
    }
    __syncwarp();

    // ---------- main: 4-lane group g = vertex vbase+g, 8 features/lane ----------
    const int g = lane >> 2;                  // 0..7
    const int sub = lane & 3;                 // 0..3
    const float4* ap = A4 + g * ASTR;
    const int*    fp = fbA + g * ASTR;
    const float* fbase = feats + sub * 8;

    unsigned long long P[8][5];
    #pragma unroll
    for (int c = 0; c < 8; ++c)
        #pragma unroll
        for (int j = 0; j < 5; ++j) P[c][j] = 0ull;

    // depth-2 pipelined feature gather (two LDG.128 per k)
    float4 fr0[2], fr1[2];
    {
        const int b0 = fp[0], b1 = fp[1];
        fr0[0] = *(const float4*)(fbase + b0);
        fr1[0] = *(const float4*)(fbase + b0 + 4);
        fr0[1] = *(const float4*)(fbase + b1);
        fr1[1] = *(const float4*)(fbase + b1 + 4);
    }

    #pragma unroll 8
    for (int k = 0; k < KN; ++k) {
        const float4 fa = fr0[k & 1];
        const float4 fb4 = fr1[k & 1];
        const int kp = (k + 2 < KN) ? (k + 2) : (KN - 1);
        const int bn = fp[kp];
        fr0[k & 1] = *(const float4*)(fbase + bn);       // prefetch k+2
        fr1[k & 1] = *(const float4*)(fbase + bn + 4);

        const float4 r = ap[k];                          // LDS.128 bcast (x,y,z,w)
        const float w = r.w, x = r.x, y = r.y, z = r.z;
        const float wx = w * x, wy = w * y, wz = w * z;
        const unsigned long long M0 = pack2(w,      wx);
        const unsigned long long M1 = pack2(wy,     wz);
        const unsigned long long M2 = pack2(wx * x, wx * y);
        const unsigned long long M3 = pack2(wx * z, wy * y);
        const unsigned long long M4 = pack2(wy * z, wz * z);

        const unsigned long long d0 = pack2(fa.x,  fa.x);
        const unsigned long long d1 = pack2(fa.y,  fa.y);
        const unsigned long long d2 = pack2(fa.z,  fa.z);
        const unsigned long long d3 = pack2(fa.w,  fa.w);
        const unsigned long long d4 = pack2(fb4.x, fb4.x);
        const unsigned long long d5 = pack2(fb4.y, fb4.y);
        const unsigned long long d6 = pack2(fb4.z, fb4.z);
        const unsigned long long d7 = pack2(fb4.w, fb4.w);

        P[0][0] = ffma2(d0, M0, P[0][0]);
        P[0][1] = ffma2(d0, M1, P[0][1]);
        P[0][2] = ffma2(d0, M2, P[0][2]);
        P[0][3] = ffma2(d0, M3, P[0][3]);
        P[0][4] = ffma2(d0, M4, P[0][4]);

        P[1][0] = ffma2(d1, M0, P[1][0]);
        P[1][1] = ffma2(d1, M1, P[1][1]);
        P[1][2] = ffma2(d1, M2, P[1][2]);
        P[1][3] = ffma2(d1, M3, P[1][3]);
        P[1][4] = ffma2(d1, M4, P[1][4]);

        P[2][0] = ffma2(d2, M0, P[2][0]);
        P[2][1] = ffma2(d2, M1, P[2][1]);
        P[2][2] = ffma2(d2, M2, P[2][2]);
        P[2][3] = ffma2(d2, M3, P[2][3]);
        P[2][4] = ffma2(d2, M4, P[2][4]);

        P[3][0] = ffma2(d3, M0, P[3][0]);
        P[3][1] = ffma2(d3, M1, P[3][1]);
        P[3][2] = ffma2(d3, M2, P[3][2]);
        P[3][3] = ffma2(d3, M3, P[3][3]);
        P[3][4] = ffma2(d3, M4, P[3][4]);

        P[4][0] = ffma2(d4, M0, P[4][0]);
        P[4][1] = ffma2(d4, M1, P[4][1]);
        P[4][2] = ffma2(d4, M2, P[4][2]);
        P[4][3] = ffma2(d4, M3, P[4][3]);
        P[4][4] = ffma2(d4, M4, P[4][4]);

        P[5][0] = ffma2(d5, M0, P[5][0]);
        P[5][1] = ffma2(d5, M1, P[5][1]);
        P[5][2] = ffma2(d5, M2, P[5][2]);
        P[5][3] = ffma2(d5, M3, P[5][3]);
        P[5][4] = ffma2(d5, M4, P[5][4]);

        P[6][0] = ffma2(d6, M0, P[6][0]);
        P[6][1] = ffma2(d6, M1, P[6][1]);
        P[6][2] = ffma2(d6, M2, P[6][2]);
        P[6][3] = ffma2(d6, M3, P[6][3]);
        P[6][4] = ffma2(d6, M4, P[6][4]);

        P[7][0] = ffma2(d7, M0, P[7][0]);
        P[7][1] = ffma2(d7, M1, P[7][1]);
        P[7][2] = ffma2(d7, M2, P[7][2]);
        P[7][3] = ffma2(d7, M3, P[7][3]);
        P[7][4] = ffma2(d7, M4, P[7][4]);
    }

    // ---------- epilogue: 4 rounds of 2 vertices ----------
    #pragma unroll
    for (int round = 0; round < 4; ++round) {
        __syncwarp();   // staging region reuses record smem; also gate prior round's reads
        if ((g >> 1) == round) {
            float* st = ws + (g & 1) * SSTR;
            #pragma unroll
            for (int half = 0; half < 2; ++half) {
                float cv[36];
                float mn[12];
                #pragma unroll
                for (int c = 0; c < 4; ++c) {
                    const int ci = half * 4 + c;
                    float S0, S1, S2, S3, S4, S5, S6, S7, S8, S9;
                    unpack2(P[ci][0], S0, S1);
                    unpack2(P[ci][1], S2, S3);
                    unpack2(P[ci][2], S4, S5);
                    unpack2(P[ci][3], S6, S7);
                    unpack2(P[ci][4], S8, S9);

                    const float inv = __fdividef(1.0f, S0 + 1e-3f);
                    const float mx = S1 * inv, my = S2 * inv, mz = S3 * inv;
                    cv[c*9+0] = fmaf(-mx, mx, S4 * inv);
                    cv[c*9+1] = fmaf(-mx, my, S5 * inv);
                    cv[c*9+2] = fmaf(-mx, mz, S6 * inv);
                    cv[c*9+4] = fmaf(-my, my, S7 * inv);
                    cv[c*9+5] = fmaf(-my, mz, S8 * inv);
                    cv[c*9+8] = fmaf(-mz, mz, S9 * inv);
                    cv[c*9+3] = cv[c*9+1];
                    cv[c*9+6] = cv[c*9+2];
                    cv[c*9+7] = cv[c*9+5];
                    mn[c*3+0] = mx; mn[c*3+1] = my; mn[c*3+2] = mz;
                }
                // features f0 = sub*8 + half*4 .. +3 ; cov block at st[f0*9], 36 floats
                float4* stc = (float4*)(st + (sub * 8 + half * 4) * 9);
                #pragma unroll
                for (int q = 0; q < 9; ++q)
                    stc[q] = *(const float4*)(cv + 4 * q);
                float4* stm = (float4*)(st + 288 + (sub * 8 + half * 4) * 3);
                #pragma unroll
                for (int q = 0; q < 3; ++q)
                    stm[q] = *(const float4*)(mn + 4 * q);
            }
        }
        __syncwarp();
        // warp-wide coalesced copy of 768 floats (2 vertices)
        float* outp = out + (size_t)(vbase + 2 * round) * 384;
        #pragma unroll
        for (int r = 0; r < 6; ++r) {
            const int e = r * 128 + lane * 4;
            const int gv = (e >= 384) ? 1 : 0;
            if (vbase + 2 * round + gv < V) {
                float4 val = *(const float4*)(ws + gv * SSTR + (e - gv * 384));
                *(float4*)(outp + e) = val;
            }
        }
    }
}

extern "C" void kernel_launch(void* const* d_in, const int* in_sizes, int n_in,
                              void* d_out, int out_size) {
    const float* coords = (const float*)d_in[0];   // V x 3
    const float* distsq = (const float*)d_in[1];   // V x 40
    const float* feats  = (const float*)d_in[2];   // V x 32
    const int*   nidx   = (const int*)d_in[3];     // V x 40
    float* out = (float*)d_out;                    // V x 384
    const int V = in_sizes[0] / 3;

    pad_coords_kernel<<<(V + 255) / 256, 256>>>(coords, V);

    const int vpb = VPW * WPB;                     // 32 vertices per block
    nbcov_kernel<<<(V + vpb - 1) / vpb, WPB * 32>>>(distsq, feats, nidx, out, V);
}